// round 4
// baseline (speedup 1.0000x reference)
#include <cuda_runtime.h>
#include <stdint.h>

// Problem constants
#define BB 4
#define XX 32
#define HH 8
#define WW 128
#define CC 32
#define NQ 128          // distinct query rows per batch
#define MM 4096         // key rows per batch
#define DD 256          // reduction dim

// ---------------------------------------------------------------------------
// Fragment-major global operand storage (pre-swizzled for mma.m16n8k8.tf32)
// A-tiles (M x 32k stage): [kt4][mt][lane32][slot4]   (4096 floats / 128-row stage)
// B-tiles (32k x N stage): [kt4][nt][lane32][slot2]
// ---------------------------------------------------------------------------
__device__ __align__(16) float g_QFh[BB*8*4096];        // Q: 8 k-stages
__device__ __align__(16) float g_QFl[BB*8*4096];
__device__ __align__(16) float g_KFh[BB*32*8*4096];     // K: [nb32][kstage8]
__device__ __align__(16) float g_KFl[BB*32*8*4096];
__device__ __align__(16) float g_VFh[BB*128*2*4096];    // V: [mchunk128][nb2]
__device__ __align__(16) float g_VFl[BB*128*2*4096];
__device__ __align__(16) float g_EFh[BB*128*4096];      // E: [mchunk128]
__device__ __align__(16) float g_EFl[BB*128*4096];
__device__ __align__(16) float g_O[BB*NQ*DD];
__device__ __align__(16) float g_rowsum[BB*NQ];
__device__ __align__(16) float g_Wh[96*72];             // presplit conv weights [k][o]
__device__ __align__(16) float g_Wl[96*72];

// ---------------------------------------------------------------------------
// helpers
// ---------------------------------------------------------------------------
__device__ __forceinline__ uint32_t f2tf(float x) {
    uint32_t h; asm("cvt.rna.tf32.f32 %0, %1;" : "=r"(h) : "f"(x)); return h;
}
__device__ __forceinline__ void sts_split(float v, float* ph, float* pl) {
    float hf = __uint_as_float(f2tf(v));
    *ph = hf;
    *pl = __uint_as_float(f2tf(v - hf));
}
__device__ __forceinline__ void mma8(float4& d, const uint32_t* a,
                                     uint32_t b0, uint32_t b1) {
    asm volatile(
        "mma.sync.aligned.m16n8k8.row.col.f32.tf32.tf32.f32 "
        "{%0,%1,%2,%3},{%4,%5,%6,%7},{%8,%9},{%0,%1,%2,%3};"
        : "+f"(d.x), "+f"(d.y), "+f"(d.z), "+f"(d.w)
        : "r"(a[0]), "r"(a[1]), "r"(a[2]), "r"(a[3]), "r"(b0), "r"(b1));
}
// frag-major index helpers: n/nl = row (or col) within tile, kc = k within 32-stage
__device__ __forceinline__ int ea_idx(int n, int kc) {
    return (kc >> 3)*1024 + (n >> 4)*128 + ((n & 7)*4 + (kc & 3))*4
         + ((n >> 3) & 1) + 2*((kc >> 2) & 1);
}
__device__ __forceinline__ int bf_idx(int nl, int kc) {
    return (kc >> 3)*1024 + (nl >> 3)*64 + ((nl & 7)*4 + (kc & 3))*2
         + ((kc >> 2) & 1);
}
__device__ __forceinline__ uint32_t smaddr(const void* p) {
    return (uint32_t)__cvta_generic_to_shared(p);
}
#define CPA(dst, src) asm volatile("cp.async.cg.shared.global [%0], [%1], 16;" \
                                   :: "r"(dst), "l"(src))
#define CP_COMMIT() asm volatile("cp.async.commit_group;")

// ---------------------------------------------------------------------------
// Kernel 1: Q projection -> frag-layout; zero g_O/g_rowsum; presplit conv wts
// ---------------------------------------------------------------------------
__global__ __launch_bounds__(256) void k_q(const float* __restrict__ target,
                                           const float* __restrict__ w_q,
                                           const float* __restrict__ b_q,
                                           const float* __restrict__ w_cross) {
    int t = blockIdx.x * 256 + threadIdx.x;       // [0, 131072)
    g_O[t] = 0.f;
    if (t < BB*NQ) g_rowsum[t] = 0.f;
    if (t < 96*72) {
        int k = t / 72, o = t - k*72;
        float v = (o < 64) ? w_cross[(o*32 + (k & 31))*3 + (k >> 5)] : 0.f;
        sts_split(v, &g_Wh[t], &g_Wl[t]);
    }

    int b   = t >> 15;
    int n   = (t >> 8) & 127;
    int cc  = t & 255;
    int o   = n >> 2, whi = n & 3;
    int wlo = cc >> 3, h = cc & 7;
    int w   = whi * 32 + wlo;
    const float4* trow = (const float4*)(target + ((b*HH + h)*WW + w)*CC);
    const float4* wrow = (const float4*)(w_q + o*CC);
    float acc = b_q[o];
#pragma unroll
    for (int i = 0; i < 8; i++) {
        float4 a = trow[i], ww = wrow[i];
        acc += a.x*ww.x + a.y*ww.y + a.z*ww.z + a.w*ww.w;
    }
    int addr = (b*8 + (cc >> 5))*4096 + ea_idx(n, cc & 31);
    sts_split(acc, &g_QFh[addr], &g_QFl[addr]);
}

// ---------------------------------------------------------------------------
// Kernel 2: conv3d (3,1,1) im2col GEMM (3xTF32); epilogue writes frag-layout
// K/V presplit. CTA = (b, w, xhalf): M=128 (16x * 8h), N=64 out-ch, K=96.
// ---------------------------------------------------------------------------
__device__ __forceinline__ void conv_store(int b, int o, int x, int wb, int cc,
                                           float v) {
    float hf = __uint_as_float(f2tf(v));
    float lf = __uint_as_float(f2tf(v - hf));
    if (o < 32) {
        int m = o*128 + x*4 + wb;
        int addr = ((b*128 + (m >> 5))*2 + (cc >> 7))*4096 + bf_idx(cc & 127, m & 31);
        g_VFh[addr] = hf; g_VFl[addr] = lf;
    } else {
        int cm = o - 32;
        int m = cm*128 + x*4 + wb;
        int addr = ((b*32 + cm)*8 + (cc >> 5))*4096 + bf_idx(m & 127, cc & 31);
        g_KFh[addr] = hf; g_KFl[addr] = lf;
    }
}

#define CONV_SMEM_FLOATS (2*18*264 + 2*96*72 + 64)
__global__ __launch_bounds__(256) void k_conv(const float* __restrict__ storage,
                                              const float* __restrict__ b_cross) {
    extern __shared__ float sm[];
    float* Sh  = sm;                    // 18*264
    float* Sl  = Sh + 18*264;
    float* Wh  = Sl + 18*264;           // 96*72
    float* Wl  = Wh + 96*72;
    float* bsh = Wl + 96*72;            // 64

    int tid  = threadIdx.x;
    int bidx = blockIdx.x;              // b*256 + w*2 + xh
    int b  = bidx >> 8;
    int w  = (bidx >> 1) & 127;
    int xh = bidx & 1;
    int x0 = xh * 16;

    {
        const float4* sh4 = (const float4*)g_Wh;
        const float4* sl4 = (const float4*)g_Wl;
        float4* dh4 = (float4*)Wh;
        float4* dl4 = (float4*)Wl;
        for (int i = tid; i < 1728; i += 256) { dh4[i] = sh4[i]; dl4[i] = sl4[i]; }
    }
    if (tid < 64) bsh[tid] = b_cross[tid];

    for (int i = tid; i < 18*64; i += 256) {
        int si = i >> 6, r = i & 63;
        int c4 = (r & 7)*4, h = r >> 3;
        int xx = x0 - 1 + si;
        float4 v = make_float4(0.f, 0.f, 0.f, 0.f);
        if (xx >= 0 && xx < XX)
            v = *(const float4*)(storage + (((b*XX + xx)*HH + h)*WW + w)*CC + c4);
        float* ph = Sh + si*264 + c4*8 + h;
        float* pl = Sl + si*264 + c4*8 + h;
        sts_split(v.x, ph +  0, pl +  0);
        sts_split(v.y, ph +  8, pl +  8);
        sts_split(v.z, ph + 16, pl + 16);
        sts_split(v.w, ph + 24, pl + 24);
    }
    __syncthreads();

    int lane = tid & 31, ww = tid >> 5;
    int lr = lane >> 2, lc = lane & 3;
    int wm = ww & 3, wn = ww >> 2;      // 4m x 2n warps; warp tile 32x32
    float4 acc[2][4];
#pragma unroll
    for (int i = 0; i < 2; i++)
#pragma unroll
        for (int j = 0; j < 4; j++) acc[i][j] = make_float4(0.f,0.f,0.f,0.f);

#pragma unroll
    for (int ksl = 0; ksl < 12; ksl++) {
        int k0 = ksl*8;
        int dx = k0 >> 5, cib = k0 & 31;
        uint32_t ah[2][4], al[2][4];
#pragma unroll
        for (int mt = 0; mt < 2; mt++) {
            int rowb = wm*32 + mt*16;
            int xl = rowb >> 3;
            const float* p = Sh + (xl + dx)*264 + (cib + lc)*8 + lr;
            ah[mt][0] = __float_as_uint(p[0]);
            ah[mt][1] = __float_as_uint(p[264]);
            ah[mt][2] = __float_as_uint(p[32]);
            ah[mt][3] = __float_as_uint(p[264+32]);
            const float* q = Sl + (xl + dx)*264 + (cib + lc)*8 + lr;
            al[mt][0] = __float_as_uint(q[0]);
            al[mt][1] = __float_as_uint(q[264]);
            al[mt][2] = __float_as_uint(q[32]);
            al[mt][3] = __float_as_uint(q[264+32]);
        }
#pragma unroll
        for (int nt = 0; nt < 4; nt++) {
            int nb = wn*32 + nt*8;
            const float* p = Wh + (k0 + lc)*72 + nb + lr;
            uint32_t bh0 = __float_as_uint(p[0]);
            uint32_t bh1 = __float_as_uint(p[4*72]);
            const float* q = Wl + (k0 + lc)*72 + nb + lr;
            uint32_t bl0 = __float_as_uint(q[0]);
            uint32_t bl1 = __float_as_uint(q[4*72]);
#pragma unroll
            for (int mt = 0; mt < 2; mt++) {
                mma8(acc[mt][nt], ah[mt], bh0, bh1);
                mma8(acc[mt][nt], ah[mt], bl0, bl1);
                mma8(acc[mt][nt], al[mt], bh0, bh1);
            }
        }
    }

    // epilogue: bias + frag-layout presplit scatter
    int wb = w >> 5;
    int cc = (w & 31)*8 + lr;           // h = lr
#pragma unroll
    for (int mt = 0; mt < 2; mt++) {
        int x = x0 + ((wm*32 + mt*16) >> 3);
#pragma unroll
        for (int nt = 0; nt < 4; nt++) {
            int o0 = wn*32 + nt*8 + lc*2;
            float4 d = acc[mt][nt];
            conv_store(b, o0,   x,   wb, cc, d.x + bsh[o0]);
            conv_store(b, o0+1, x,   wb, cc, d.y + bsh[o0+1]);
            conv_store(b, o0,   x+1, wb, cc, d.z + bsh[o0]);
            conv_store(b, o0+1, x+1, wb, cc, d.w + bsh[o0+1]);
        }
    }
}

// ---------------------------------------------------------------------------
// Stage copy for GEMM kernels: 16KB hi/lo A + hi/lo B, linear cp.async
// buf layout: [Ah 4096][Al 4096][Bh 4096][Bl 4096]
// ---------------------------------------------------------------------------
__device__ __forceinline__ void copy_stage(float* buf,
                                           const float* Ah, const float* Al,
                                           const float* Bh, const float* Bl,
                                           int tid) {
#pragma unroll
    for (int k = 0; k < 4; k++) {
        int i = (tid + k*256)*4;
        CPA(smaddr(buf + i),         Ah + i);
        CPA(smaddr(buf + 4096 + i),  Al + i);
        CPA(smaddr(buf + 8192 + i),  Bh + i);
        CPA(smaddr(buf + 12288 + i), Bl + i);
    }
    CP_COMMIT();
}

// compute one 32-k stage: warp tile 64m x 32n, frags via LDS.128/LDS.64
__device__ __forceinline__ void stage_mma(const float* buf, float4 acc[4][4],
                                          int lane, int wm, int wn) {
#pragma unroll
    for (int kt = 0; kt < 4; kt++) {
        float4 ah[4], al[4];
        const float* Ab = buf + kt*1024 + lane*4;
#pragma unroll
        for (int mt = 0; mt < 4; mt++) {
            ah[mt] = *(const float4*)(Ab + (wm*4 + mt)*128);
            al[mt] = *(const float4*)(Ab + 4096 + (wm*4 + mt)*128);
        }
#pragma unroll
        for (int nt = 0; nt < 4; nt++) {
            const float* Bb = buf + 8192 + kt*1024 + (wn*4 + nt)*64 + lane*2;
            float2 bh = *(const float2*)(Bb);
            float2 bl = *(const float2*)(Bb + 4096);
            uint32_t bh0 = __float_as_uint(bh.x), bh1 = __float_as_uint(bh.y);
            uint32_t bl0 = __float_as_uint(bl.x), bl1 = __float_as_uint(bl.y);
#pragma unroll
            for (int mt = 0; mt < 4; mt++) {
                mma8(acc[mt][nt], (const uint32_t*)&ah[mt], bh0, bh1);
                mma8(acc[mt][nt], (const uint32_t*)&ah[mt], bl0, bl1);
                mma8(acc[mt][nt], (const uint32_t*)&al[mt], bh0, bh1);
            }
        }
    }
}

// ---------------------------------------------------------------------------
// Kernel 3: S = Q @ K^T (3xTF32), cp.async double-buffered; fused exp +
// rowsum; E written in frag layout via smem staging, coalesced flush.
// ---------------------------------------------------------------------------
#define GEMM_SMEM_BYTES (2*16384*4)
__global__ __launch_bounds__(256) void k_gemm1() {
    extern __shared__ float sm[];
    __shared__ float srow[128];
    int tid = threadIdx.x;
    int b  = blockIdx.x >> 5;
    int nb = blockIdx.x & 31;
    const float* Ah0 = g_QFh + b*8*4096;
    const float* Al0 = g_QFl + b*8*4096;
    const float* Bh0 = g_KFh + (b*32 + nb)*8*4096;
    const float* Bl0 = g_KFl + (b*32 + nb)*8*4096;

    int lane = tid & 31, ww = tid >> 5;
    int lr = lane >> 2, lc = lane & 3;
    int wm = ww & 1, wn = ww >> 1;
    float4 acc[4][4];
#pragma unroll
    for (int i = 0; i < 4; i++)
#pragma unroll
        for (int j = 0; j < 4; j++) acc[i][j] = make_float4(0.f,0.f,0.f,0.f);

    copy_stage(sm, Ah0, Al0, Bh0, Bl0, tid);
    for (int s = 0; s < 8; s++) {
        if (s < 7)
            copy_stage(sm + ((s+1)&1)*16384, Ah0 + (s+1)*4096, Al0 + (s+1)*4096,
                       Bh0 + (s+1)*4096, Bl0 + (s+1)*4096, tid);
        if (s < 7) asm volatile("cp.async.wait_group 1;");
        else       asm volatile("cp.async.wait_group 0;");
        __syncthreads();
        stage_mma(sm + (s&1)*16384, acc, lane, wm, wn);
        __syncthreads();
    }

    // epilogue: exp, rowsum, frag-layout E via smem
    if (tid < 128) srow[tid] = 0.f;
    __syncthreads();
    float* Esh = sm;
    float* Esl = sm + 16384;
    float rs[8] = {0.f,0.f,0.f,0.f,0.f,0.f,0.f,0.f};
#pragma unroll
    for (int mt = 0; mt < 4; mt++) {
#pragma unroll
        for (int nt = 0; nt < 4; nt++) {
            int row0 = wm*64 + mt*16 + lr;
            int col0 = wn*32 + nt*8 + lc*2;
            float4 d = acc[mt][nt];
            float e0 = __expf(d.x), e1 = __expf(d.y);
            float e2 = __expf(d.z), e3 = __expf(d.w);
            rs[mt*2+0] += e0 + e1;
            rs[mt*2+1] += e2 + e3;
            sts_split(e0, &Esh[wn*4096 + ea_idx(row0,   col0 & 31)],
                          &Esl[wn*4096 + ea_idx(row0,   col0 & 31)]);
            sts_split(e1, &Esh[wn*4096 + ea_idx(row0,   (col0+1) & 31)],
                          &Esl[wn*4096 + ea_idx(row0,   (col0+1) & 31)]);
            sts_split(e2, &Esh[wn*4096 + ea_idx(row0+8, col0 & 31)],
                          &Esl[wn*4096 + ea_idx(row0+8, col0 & 31)]);
            sts_split(e3, &Esh[wn*4096 + ea_idx(row0+8, (col0+1) & 31)],
                          &Esl[wn*4096 + ea_idx(row0+8, (col0+1) & 31)]);
        }
    }
#pragma unroll
    for (int i = 0; i < 8; i++) {
        rs[i] += __shfl_xor_sync(~0u, rs[i], 1);
        rs[i] += __shfl_xor_sync(~0u, rs[i], 2);
    }
    if (lc == 0) {
#pragma unroll
        for (int i = 0; i < 8; i++)
            atomicAdd(&srow[wm*64 + (i >> 1)*16 + (i & 1)*8 + lr], rs[i]);
    }
    __syncthreads();
    if (tid < 128) atomicAdd(&g_rowsum[b*128 + tid], srow[tid]);

    float* dsth = g_EFh + (b*128 + nb*4)*4096;
    float* dstl = g_EFl + (b*128 + nb*4)*4096;
#pragma unroll
    for (int k = 0; k < 16; k++) {
        int i = (tid + k*256)*4;
        *(float4*)(dsth + i) = *(const float4*)(Esh + i);
        *(float4*)(dstl + i) = *(const float4*)(Esl + i);
    }
}

// ---------------------------------------------------------------------------
// Kernel 4: O += E @ V (3xTF32), cp.async double-buffered, split-K atomics.
// grid = b4 x nb2 x ks16; K-split = 256 (8 stages of 32).
// ---------------------------------------------------------------------------
__global__ __launch_bounds__(256) void k_gemm2() {
    extern __shared__ float sm[];
    int tid = threadIdx.x;
    int b  = blockIdx.x >> 5;
    int nb = (blockIdx.x >> 4) & 1;
    int ks = blockIdx.x & 15;
    int c0 = ks*8;                     // first m-chunk

    int lane = tid & 31, ww = tid >> 5;
    int lr = lane >> 2, lc = lane & 3;
    int wm = ww & 1, wn = ww >> 1;
    float4 acc[4][4];
#pragma unroll
    for (int i = 0; i < 4; i++)
#pragma unroll
        for (int j = 0; j < 4; j++) acc[i][j] = make_float4(0.f,0.f,0.f,0.f);

    const float* Ah0 = g_EFh + (b*128 + c0)*4096;
    const float* Al0 = g_EFl + (b*128 + c0)*4096;
    // B stages: ((b*128 + c)*2 + nb)*4096, stride per stage = 2*4096
    const float* Bh0 = g_VFh + ((b*128 + c0)*2 + nb)*4096;
    const float* Bl0 = g_VFl + ((b*128 + c0)*2 + nb)*4096;

    copy_stage(sm, Ah0, Al0, Bh0, Bl0, tid);
    for (int s = 0; s < 8; s++) {
        if (s < 7)
            copy_stage(sm + ((s+1)&1)*16384,
                       Ah0 + (s+1)*4096,   Al0 + (s+1)*4096,
                       Bh0 + (s+1)*8192,   Bl0 + (s+1)*8192, tid);
        if (s < 7) asm volatile("cp.async.wait_group 1;");
        else       asm volatile("cp.async.wait_group 0;");
        __syncthreads();
        stage_mma(sm + (s&1)*16384, acc, lane, wm, wn);
        __syncthreads();
    }

    float* Og = g_O + b*NQ*DD + nb*128;
#pragma unroll
    for (int mt = 0; mt < 4; mt++) {
#pragma unroll
        for (int nt = 0; nt < 4; nt++) {
            int row = wm*64 + mt*16 + lr;
            int col = wn*32 + nt*8 + lc*2;
            float4 d = acc[mt][nt];
            atomicAdd(Og + row*DD + col,       d.x);
            atomicAdd(Og + row*DD + col + 1,   d.y);
            atomicAdd(Og + (row+8)*DD + col,   d.z);
            atomicAdd(Og + (row+8)*DD + col+1, d.w);
        }
    }
}

// ---------------------------------------------------------------------------
// Kernel 5: normalize + scatter to output [B,X,H,W,C], float4.
// ---------------------------------------------------------------------------
__global__ __launch_bounds__(256) void k_out(float* __restrict__ out) {
    int t4 = blockIdx.x*256 + threadIdx.x;
    int t  = t4 * 4;
    int co = t & 31;
    int wo = (t >> 5) & 127;
    int xo = (t >> 15) & 31;
    int b  = t >> 20;
    int n  = xo*4 + ((wo >> 3) & 3);
    int cc = ((wo & 7)*4 + (co >> 3))*8 + (co & 7);
    float inv = __fdividef(1.f, g_rowsum[b*128 + n]);
    float4 v = *(const float4*)(g_O + (b*NQ + n)*DD + cc);
    v.x *= inv; v.y *= inv; v.z *= inv; v.w *= inv;
    *(float4*)(out + t) = v;
}

// ---------------------------------------------------------------------------
extern "C" void kernel_launch(void* const* d_in, const int* in_sizes, int n_in,
                              void* d_out, int out_size) {
    const float* storage = (const float*)d_in[0];
    const float* target  = (const float*)d_in[1];
    const float* w_cross = (const float*)d_in[2];
    const float* b_cross = (const float*)d_in[3];
    const float* w_q     = (const float*)d_in[4];
    const float* b_q     = (const float*)d_in[5];
    float* out = (float*)d_out;

    cudaFuncSetAttribute(k_conv,  cudaFuncAttributeMaxDynamicSharedMemorySize,
                         CONV_SMEM_FLOATS * 4);
    cudaFuncSetAttribute(k_gemm1, cudaFuncAttributeMaxDynamicSharedMemorySize,
                         GEMM_SMEM_BYTES);
    cudaFuncSetAttribute(k_gemm2, cudaFuncAttributeMaxDynamicSharedMemorySize,
                         GEMM_SMEM_BYTES);

    k_q    <<<512,  256>>>(target, w_q, b_q, w_cross);
    k_conv <<<1024, 256, CONV_SMEM_FLOATS*4>>>(storage, b_cross);
    k_gemm1<<<128,  256, GEMM_SMEM_BYTES>>>();
    k_gemm2<<<128,  256, GEMM_SMEM_BYTES>>>();
    k_out  <<<4096, 256>>>(out);
}

// round 5
// speedup vs baseline: 1.1659x; 1.1659x over previous
#include <cuda_runtime.h>
#include <stdint.h>

// Problem constants
#define BB 4
#define XX 32
#define HH 8
#define WW 128
#define CC 32
#define NQ 128          // distinct query rows per batch
#define MM 4096         // key rows per batch
#define DD 256          // reduction dim

// Scratch (plain fp32 row-major everywhere)
__device__ __align__(16) float g_Q [BB*NQ*DD];    // [b][n][cc]
__device__ __align__(16) float g_K [BB*MM*DD];    // [b][m][cc]
__device__ __align__(16) float g_V [BB*MM*DD];    // [b][m][cc]
__device__ __align__(16) float g_Vt[BB*DD*MM];    // [b][cc][m]
__device__ __align__(16) float g_E [BB*NQ*MM];    // [b][n][m] = exp(S)
__device__ __align__(16) float g_O [BB*NQ*DD];
__device__ __align__(16) float g_rowsum[BB*NQ];
__device__ __align__(16) float g_Wh[96*72];       // presplit conv weights [k][o]
__device__ __align__(16) float g_Wl[96*72];

// ---------------------------------------------------------------------------
// helpers
// ---------------------------------------------------------------------------
__device__ __forceinline__ uint32_t f2tf(float x) {
    uint32_t h; asm("cvt.rna.tf32.f32 %0, %1;" : "=r"(h) : "f"(x)); return h;
}
__device__ __forceinline__ void sts_split(float v, float* ph, float* pl) {
    float hf = __uint_as_float(f2tf(v));
    *ph = hf;
    *pl = __uint_as_float(f2tf(v - hf));
}
__device__ __forceinline__ void mma8(float4& d, const uint32_t* a,
                                     uint32_t b0, uint32_t b1) {
    asm volatile(
        "mma.sync.aligned.m16n8k8.row.col.f32.tf32.tf32.f32 "
        "{%0,%1,%2,%3},{%4,%5,%6,%7},{%8,%9},{%0,%1,%2,%3};"
        : "+f"(d.x), "+f"(d.y), "+f"(d.z), "+f"(d.w)
        : "r"(a[0]), "r"(a[1]), "r"(a[2]), "r"(a[3]), "r"(b0), "r"(b1));
}
__device__ __forceinline__ uint32_t smaddr(const void* p) {
    return (uint32_t)__cvta_generic_to_shared(p);
}
__device__ __forceinline__ void ldsm4(uint32_t r[4], const float* p) {
    uint32_t a = smaddr(p);
    asm volatile("ldmatrix.sync.aligned.m8n8.x4.shared.b16 {%0,%1,%2,%3}, [%4];"
                 : "=r"(r[0]), "=r"(r[1]), "=r"(r[2]), "=r"(r[3]) : "r"(a));
}
__device__ __forceinline__ void ldsm2(uint32_t r[2], const float* p) {
    uint32_t a = smaddr(p);
    asm volatile("ldmatrix.sync.aligned.m8n8.x2.shared.b16 {%0,%1}, [%2];"
                 : "=r"(r[0]), "=r"(r[1]) : "r"(a));
}
#define CPA(dst, src) asm volatile("cp.async.cg.shared.global [%0], [%1], 16;" \
                                   :: "r"(dst), "l"(src))
#define CP_COMMIT() asm volatile("cp.async.commit_group;")

// ---------------------------------------------------------------------------
// Kernel 1: Q projection (plain fp32) + zero g_O/g_rowsum + presplit conv wts
// ---------------------------------------------------------------------------
__global__ __launch_bounds__(256) void k_q(const float* __restrict__ target,
                                           const float* __restrict__ w_q,
                                           const float* __restrict__ b_q,
                                           const float* __restrict__ w_cross) {
    int t = blockIdx.x * 256 + threadIdx.x;       // [0, 131072)
    g_O[t] = 0.f;
    if (t < BB*NQ) g_rowsum[t] = 0.f;
    if (t < 96*72) {
        int k = t / 72, o = t - k*72;
        float v = (o < 64) ? w_cross[(o*32 + (k & 31))*3 + (k >> 5)] : 0.f;
        sts_split(v, &g_Wh[t], &g_Wl[t]);
    }

    int b   = t >> 15;
    int n   = (t >> 8) & 127;
    int cc  = t & 255;
    int o   = n >> 2, whi = n & 3;
    int wlo = cc >> 3, h = cc & 7;
    int w   = whi * 32 + wlo;
    const float4* trow = (const float4*)(target + ((b*HH + h)*WW + w)*CC);
    const float4* wrow = (const float4*)(w_q + o*CC);
    float acc = b_q[o];
#pragma unroll
    for (int i = 0; i < 8; i++) {
        float4 a = trow[i], ww = wrow[i];
        acc += a.x*ww.x + a.y*ww.y + a.z*ww.z + a.w*ww.w;
    }
    g_Q[t] = acc;
}

// ---------------------------------------------------------------------------
// Kernel 2: conv3d (3,1,1) im2col GEMM (3xTF32). Plain row-major K/V stores.
// CTA = (b, w, xhalf): M=128 (16x * 8h), N=64 out-ch, K=96.
// ---------------------------------------------------------------------------
#define CONV_SMEM_FLOATS (2*18*264 + 2*96*72 + 64)
__global__ __launch_bounds__(256) void k_conv(const float* __restrict__ storage,
                                              const float* __restrict__ b_cross) {
    extern __shared__ float sm[];
    float* Sh  = sm;                    // 18*264
    float* Sl  = Sh + 18*264;
    float* Wh  = Sl + 18*264;           // 96*72
    float* Wl  = Wh + 96*72;
    float* bsh = Wl + 96*72;            // 64

    int tid  = threadIdx.x;
    int bidx = blockIdx.x;              // b*256 + w*2 + xh
    int b  = bidx >> 8;
    int w  = (bidx >> 1) & 127;
    int xh = bidx & 1;
    int x0 = xh * 16;

    {
        const float4* sh4 = (const float4*)g_Wh;
        const float4* sl4 = (const float4*)g_Wl;
        float4* dh4 = (float4*)Wh;
        float4* dl4 = (float4*)Wl;
        for (int i = tid; i < 1728; i += 256) { dh4[i] = sh4[i]; dl4[i] = sl4[i]; }
    }
    if (tid < 64) bsh[tid] = b_cross[tid];

    for (int i = tid; i < 18*64; i += 256) {
        int si = i >> 6, r = i & 63;
        int c4 = (r & 7)*4, h = r >> 3;
        int xx = x0 - 1 + si;
        float4 v = make_float4(0.f, 0.f, 0.f, 0.f);
        if (xx >= 0 && xx < XX)
            v = *(const float4*)(storage + (((b*XX + xx)*HH + h)*WW + w)*CC + c4);
        float* ph = Sh + si*264 + c4*8 + h;
        float* pl = Sl + si*264 + c4*8 + h;
        sts_split(v.x, ph +  0, pl +  0);
        sts_split(v.y, ph +  8, pl +  8);
        sts_split(v.z, ph + 16, pl + 16);
        sts_split(v.w, ph + 24, pl + 24);
    }
    __syncthreads();

    int lane = tid & 31, ww = tid >> 5;
    int lr = lane >> 2, lc = lane & 3;
    int wm = ww & 3, wn = ww >> 2;      // 4m x 2n warps; warp tile 32x32
    float4 acc[2][4];
#pragma unroll
    for (int i = 0; i < 2; i++)
#pragma unroll
        for (int j = 0; j < 4; j++) acc[i][j] = make_float4(0.f,0.f,0.f,0.f);

#pragma unroll
    for (int ksl = 0; ksl < 12; ksl++) {
        int k0 = ksl*8;
        int dx = k0 >> 5, cib = k0 & 31;
        uint32_t ah[2][4], al[2][4];
#pragma unroll
        for (int mt = 0; mt < 2; mt++) {
            int rowb = wm*32 + mt*16;
            int xl = rowb >> 3;
            const float* p = Sh + (xl + dx)*264 + (cib + lc)*8 + lr;
            ah[mt][0] = __float_as_uint(p[0]);
            ah[mt][1] = __float_as_uint(p[264]);
            ah[mt][2] = __float_as_uint(p[32]);
            ah[mt][3] = __float_as_uint(p[264+32]);
            const float* q = Sl + (xl + dx)*264 + (cib + lc)*8 + lr;
            al[mt][0] = __float_as_uint(q[0]);
            al[mt][1] = __float_as_uint(q[264]);
            al[mt][2] = __float_as_uint(q[32]);
            al[mt][3] = __float_as_uint(q[264+32]);
        }
#pragma unroll
        for (int nt = 0; nt < 4; nt++) {
            int nb = wn*32 + nt*8;
            const float* p = Wh + (k0 + lc)*72 + nb + lr;
            uint32_t bh0 = __float_as_uint(p[0]);
            uint32_t bh1 = __float_as_uint(p[4*72]);
            const float* q = Wl + (k0 + lc)*72 + nb + lr;
            uint32_t bl0 = __float_as_uint(q[0]);
            uint32_t bl1 = __float_as_uint(q[4*72]);
#pragma unroll
            for (int mt = 0; mt < 2; mt++) {
                mma8(acc[mt][nt], ah[mt], bh0, bh1);
                mma8(acc[mt][nt], ah[mt], bl0, bl1);
                mma8(acc[mt][nt], al[mt], bh0, bh1);
            }
        }
    }

    // epilogue: bias + plain row-major scatter
    int wb = w >> 5, ccb = (w & 31)*8;
#pragma unroll
    for (int mt = 0; mt < 2; mt++) {
        int rowb = wm*32 + mt*16;
        int x = x0 + (rowb >> 3);
        int h = lr;
#pragma unroll
        for (int nt = 0; nt < 4; nt++) {
            int o0 = wn*32 + nt*8 + lc*2;
            float4 d = acc[mt][nt];
            {
                float v0 = d.x + bsh[o0], v1 = d.y + bsh[o0+1];
                float* d0 = (o0     < 32) ? g_V : g_K;
                float* d1 = (o0 + 1 < 32) ? g_V : g_K;
                d0[(b*MM + (o0&31)*128     + x*4 + wb)*DD + ccb + h] = v0;
                d1[(b*MM + ((o0+1)&31)*128 + x*4 + wb)*DD + ccb + h] = v1;
            }
            {
                float v0 = d.z + bsh[o0], v1 = d.w + bsh[o0+1];
                float* d0 = (o0     < 32) ? g_V : g_K;
                float* d1 = (o0 + 1 < 32) ? g_V : g_K;
                d0[(b*MM + (o0&31)*128     + (x+1)*4 + wb)*DD + ccb + h] = v0;
                d1[(b*MM + ((o0+1)&31)*128 + (x+1)*4 + wb)*DD + ccb + h] = v1;
            }
        }
    }
}

// ---------------------------------------------------------------------------
// Kernel 3: V transpose  [b][m][cc] -> [b][cc][m], 64x64 tiles, coalesced.
// ---------------------------------------------------------------------------
__global__ __launch_bounds__(256) void k_vt() {
    __shared__ float ts[64*65];
    int tid = threadIdx.x;
    int b  = blockIdx.x >> 8;
    int mt = (blockIdx.x >> 2) & 63;
    int ct = blockIdx.x & 3;
#pragma unroll
    for (int it = 0; it < 4; it++) {
        int i = tid + it*256;               // 0..1023
        int r = i >> 4, c4 = (i & 15)*4;
        float4 v = *(const float4*)(g_V + (b*MM + mt*64 + r)*DD + ct*64 + c4);
        ts[r*65 + c4 + 0] = v.x; ts[r*65 + c4 + 1] = v.y;
        ts[r*65 + c4 + 2] = v.z; ts[r*65 + c4 + 3] = v.w;
    }
    __syncthreads();
#pragma unroll
    for (int it = 0; it < 4; it++) {
        int i = tid + it*256;
        int c = i >> 4, r4 = (i & 15)*4;
        float4 o = make_float4(ts[(r4+0)*65 + c], ts[(r4+1)*65 + c],
                               ts[(r4+2)*65 + c], ts[(r4+3)*65 + c]);
        *(float4*)(g_Vt + (b*DD + ct*64 + c)*MM + mt*64 + r4) = o;
    }
}

// ---------------------------------------------------------------------------
// Shared GEMM machinery: row-major fp32 smem tiles [128][32] stride 36,
// cp.async staging, ldmatrix frags, in-register 3xTF32 split.
// ---------------------------------------------------------------------------
#define ASTR 36
#define STAGE_FLOATS (2*128*ASTR)           // A + B tile = 9216
#define GEMM_SMEM_BYTES (2*STAGE_FLOATS*4)  // double buffered = 73728 B

__device__ __forceinline__ void copy_stage(float* buf, const float* Ag, int lda,
                                           const float* Bg, int ldb, int tid) {
#pragma unroll
    for (int ch = 0; ch < 4; ch++) {
        int c = tid + ch*256;               // 0..1023
        int row = c >> 3, k4 = (c & 7)*4;
        CPA(smaddr(buf + row*ASTR + k4),            Ag + row*lda + k4);
        CPA(smaddr(buf + 128*ASTR + row*ASTR + k4), Bg + row*ldb + k4);
    }
    CP_COMMIT();
}

__device__ __forceinline__ void stage_mma(const float* buf, float4 acc[4][4],
                                          int lane, int wm, int wn) {
    const float* As = buf;
    const float* Bs = buf + 128*ASTR;
    int arow = (lane & 7) + ((lane >> 3) & 1)*8;
    int acol = (lane >> 4)*4;
    int bl   = lane & 15;
    int brow = bl & 7;
    int bcol = (bl >> 3)*4;
#pragma unroll
    for (int kt = 0; kt < 4; kt++) {
        int kk = kt*8;
        uint32_t ahH[4][4], ahL[4][4];
#pragma unroll
        for (int mt = 0; mt < 4; mt++) {
            int rb = wm*64 + mt*16;
            uint32_t ar[4];
            ldsm4(ar, As + (rb + arow)*ASTR + kk + acol);
#pragma unroll
            for (int i = 0; i < 4; i++) {
                float f = __uint_as_float(ar[i]);
                uint32_t h = f2tf(f);
                ahH[mt][i] = h;
                ahL[mt][i] = f2tf(f - __uint_as_float(h));
            }
        }
#pragma unroll
        for (int nt = 0; nt < 4; nt++) {
            int nrb = wn*32 + nt*8;
            uint32_t br[2];
            ldsm2(br, Bs + (nrb + brow)*ASTR + kk + bcol);
            float f0 = __uint_as_float(br[0]), f1 = __uint_as_float(br[1]);
            uint32_t bh0 = f2tf(f0), bh1 = f2tf(f1);
            uint32_t bL0 = f2tf(f0 - __uint_as_float(bh0));
            uint32_t bL1 = f2tf(f1 - __uint_as_float(bh1));
#pragma unroll
            for (int mt = 0; mt < 4; mt++) {
                mma8(acc[mt][nt], ahH[mt], bh0, bh1);
                mma8(acc[mt][nt], ahH[mt], bL0, bL1);
                mma8(acc[mt][nt], ahL[mt], bh0, bh1);
            }
        }
    }
}

// ---------------------------------------------------------------------------
// Kernel 4: S = Q @ K^T (3xTF32), fused exp + rowsum, E plain fp32 out.
// grid = b(4) x nb(32); CTA tile 128n x 128m; K = 256 (8 stages of 32).
// ---------------------------------------------------------------------------
__global__ __launch_bounds__(256, 2) void k_gemm1() {
    extern __shared__ float sm[];
    __shared__ float srow[128];
    int tid = threadIdx.x;
    int b  = blockIdx.x >> 5;
    int nb = blockIdx.x & 31;
    const float* Ag = g_Q + b*NQ*DD;                 // [128][256]
    const float* Bg = g_K + (b*MM + nb*128)*DD;      // [128][256]

    int lane = tid & 31, ww = tid >> 5;
    int lr = lane >> 2, lc = lane & 3;
    int wm = ww & 1, wn = ww >> 1;
    float4 acc[4][4];
#pragma unroll
    for (int i = 0; i < 4; i++)
#pragma unroll
        for (int j = 0; j < 4; j++) acc[i][j] = make_float4(0.f,0.f,0.f,0.f);

    copy_stage(sm, Ag, DD, Bg, DD, tid);
    for (int s = 0; s < 8; s++) {
        if (s < 7)
            copy_stage(sm + ((s+1)&1)*STAGE_FLOATS,
                       Ag + (s+1)*32, DD, Bg + (s+1)*32, DD, tid);
        if (s < 7) asm volatile("cp.async.wait_group 1;");
        else       asm volatile("cp.async.wait_group 0;");
        __syncthreads();
        stage_mma(sm + (s&1)*STAGE_FLOATS, acc, lane, wm, wn);
        __syncthreads();
    }

    // epilogue: exp, rowsum, plain E store
    if (tid < 128) srow[tid] = 0.f;
    __syncthreads();
    float* Eg = g_E + b*NQ*MM + nb*128;
    float rs[8] = {0.f,0.f,0.f,0.f,0.f,0.f,0.f,0.f};
#pragma unroll
    for (int mt = 0; mt < 4; mt++) {
#pragma unroll
        for (int nt = 0; nt < 4; nt++) {
            int row = wm*64 + mt*16 + lr;
            int col = wn*32 + nt*8 + lc*2;
            float4 d = acc[mt][nt];
            float e0 = __expf(d.x), e1 = __expf(d.y);
            float e2 = __expf(d.z), e3 = __expf(d.w);
            rs[mt*2+0] += e0 + e1;
            rs[mt*2+1] += e2 + e3;
            *(float2*)(Eg + row*MM + col)     = make_float2(e0, e1);
            *(float2*)(Eg + (row+8)*MM + col) = make_float2(e2, e3);
        }
    }
#pragma unroll
    for (int i = 0; i < 8; i++) {
        rs[i] += __shfl_xor_sync(~0u, rs[i], 1);
        rs[i] += __shfl_xor_sync(~0u, rs[i], 2);
    }
    if (lc == 0) {
#pragma unroll
        for (int i = 0; i < 8; i++)
            atomicAdd(&srow[wm*64 + (i >> 1)*16 + (i & 1)*8 + lr], rs[i]);
    }
    __syncthreads();
    if (tid < 128) atomicAdd(&g_rowsum[b*128 + tid], srow[tid]);
}

// ---------------------------------------------------------------------------
// Kernel 5: O += E @ V (3xTF32), split-K(m) atomics.
// grid = b(4) x nb(2: cc-halves) x ks(16: 256-k splits).
// A = E [n][m] row-major; B = Vt [cc][m] row-major -> both ldmatrix-native.
// ---------------------------------------------------------------------------
__global__ __launch_bounds__(256, 2) void k_gemm2() {
    extern __shared__ float sm[];
    int tid = threadIdx.x;
    int b  = blockIdx.x >> 5;
    int nb = (blockIdx.x >> 4) & 1;
    int ks = blockIdx.x & 15;
    const float* Ag = g_E  + b*NQ*MM + ks*256;               // [128][m] ld=MM
    const float* Bg = g_Vt + (b*DD + nb*128)*MM + ks*256;    // [128][m] ld=MM

    int lane = tid & 31, ww = tid >> 5;
    int lr = lane >> 2, lc = lane & 3;
    int wm = ww & 1, wn = ww >> 1;
    float4 acc[4][4];
#pragma unroll
    for (int i = 0; i < 4; i++)
#pragma unroll
        for (int j = 0; j < 4; j++) acc[i][j] = make_float4(0.f,0.f,0.f,0.f);

    copy_stage(sm, Ag, MM, Bg, MM, tid);
    for (int s = 0; s < 8; s++) {
        if (s < 7)
            copy_stage(sm + ((s+1)&1)*STAGE_FLOATS,
                       Ag + (s+1)*32, MM, Bg + (s+1)*32, MM, tid);
        if (s < 7) asm volatile("cp.async.wait_group 1;");
        else       asm volatile("cp.async.wait_group 0;");
        __syncthreads();
        stage_mma(sm + (s&1)*STAGE_FLOATS, acc, lane, wm, wn);
        __syncthreads();
    }

    float* Og = g_O + b*NQ*DD + nb*128;
#pragma unroll
    for (int mt = 0; mt < 4; mt++) {
#pragma unroll
        for (int nt = 0; nt < 4; nt++) {
            int row = wm*64 + mt*16 + lr;
            int col = wn*32 + nt*8 + lc*2;
            float4 d = acc[mt][nt];
            atomicAdd(Og + row*DD + col,       d.x);
            atomicAdd(Og + row*DD + col + 1,   d.y);
            atomicAdd(Og + (row+8)*DD + col,   d.z);
            atomicAdd(Og + (row+8)*DD + col+1, d.w);
        }
    }
}

// ---------------------------------------------------------------------------
// Kernel 6: normalize + scatter to output [B,X,H,W,C], float4.
// ---------------------------------------------------------------------------
__global__ __launch_bounds__(256) void k_out(float* __restrict__ out) {
    int t4 = blockIdx.x*256 + threadIdx.x;
    int t  = t4 * 4;
    int co = t & 31;
    int wo = (t >> 5) & 127;
    int xo = (t >> 15) & 31;
    int b  = t >> 20;
    int n  = xo*4 + ((wo >> 3) & 3);
    int cc = ((wo & 7)*4 + (co >> 3))*8 + (co & 7);
    float inv = __fdividef(1.f, g_rowsum[b*128 + n]);
    float4 v = *(const float4*)(g_O + (b*NQ + n)*DD + cc);
    v.x *= inv; v.y *= inv; v.z *= inv; v.w *= inv;
    *(float4*)(out + t) = v;
}

// ---------------------------------------------------------------------------
extern "C" void kernel_launch(void* const* d_in, const int* in_sizes, int n_in,
                              void* d_out, int out_size) {
    const float* storage = (const float*)d_in[0];
    const float* target  = (const float*)d_in[1];
    const float* w_cross = (const float*)d_in[2];
    const float* b_cross = (const float*)d_in[3];
    const float* w_q     = (const float*)d_in[4];
    const float* b_q     = (const float*)d_in[5];
    float* out = (float*)d_out;

    cudaFuncSetAttribute(k_conv,  cudaFuncAttributeMaxDynamicSharedMemorySize,
                         CONV_SMEM_FLOATS * 4);
    cudaFuncSetAttribute(k_gemm1, cudaFuncAttributeMaxDynamicSharedMemorySize,
                         GEMM_SMEM_BYTES);
    cudaFuncSetAttribute(k_gemm2, cudaFuncAttributeMaxDynamicSharedMemorySize,
                         GEMM_SMEM_BYTES);

    k_q    <<<512,  256>>>(target, w_q, b_q, w_cross);
    k_conv <<<1024, 256, CONV_SMEM_FLOATS*4>>>(storage, b_cross);
    k_vt   <<<1024, 256>>>();
    k_gemm1<<<128,  256, GEMM_SMEM_BYTES>>>();
    k_gemm2<<<128,  256, GEMM_SMEM_BYTES>>>();
    k_out  <<<4096, 256>>>(out);
}